// round 12
// baseline (speedup 1.0000x reference)
#include <cuda_runtime.h>
#include <cuda_bf16.h>
#include <cstdint>

#define NN    100000
#define RR    7
#define DD    64
#define EDIM  16
#define KU    448              // R*D
#define KTOT  512              // 448 (U) + 64 (x)

typedef unsigned long long ull;

// Scratch
__device__ float g_U[(size_t)NN * KU];              // 179.2 MB
// Combined weights: g_Wq[kk*64 + col] = float4 of Wcomb[col][4kk..4kk+3],
//   Wcomb[col][k] = k<448 ? W_lin[col][k] : W_self[col][k-448]
__device__ float4 g_Wq[128 * 64];                   // 128 KB
__device__ float  g_bias[DD];

// ---- f32x2 helpers (sm_103a packed FMA) -----------------------------------
__device__ __forceinline__ ull f2fma(ull a, ull b, ull c) {
    ull d; asm("fma.rn.f32x2 %0, %1, %2, %3;" : "=l"(d) : "l"(a), "l"(b), "l"(c)); return d;
}
__device__ __forceinline__ ull pk2(float w) {
    ull r; asm("mov.b64 %0, {%1, %1};" : "=l"(r) : "f"(w)); return r;
}
__device__ __forceinline__ float2 up2(ull v) {
    float2 r; asm("mov.b64 {%0, %1}, %2;" : "=f"(r.x), "=f"(r.y) : "l"(v)); return r;
}

// ---------------------------------------------------------------------------
// K0: build combined weight (float4 per (kk, col)) + bias
// ---------------------------------------------------------------------------
__global__ void prep_kernel(const float* __restrict__ W_lin,  const float* __restrict__ b_lin,
                            const float* __restrict__ W_self, const float* __restrict__ b_self) {
    int tid = blockIdx.x * blockDim.x + threadIdx.x;
    const int total = 128 * 64;
    for (int idx = tid; idx < total; idx += gridDim.x * blockDim.x) {
        int kk  = idx >> 6;
        int col = idx & 63;
        float t[4];
#pragma unroll
        for (int j = 0; j < 4; j++) {
            int k = 4 * kk + j;
            t[j] = (k < KU) ? W_lin[col * KU + k]
                            : W_self[col * DD + (k - KU)];
        }
        g_Wq[idx] = make_float4(t[0], t[1], t[2], t[3]);
    }
    if (tid < DD) g_bias[tid] = b_lin[tid] + b_self[tid];
}

// ---------------------------------------------------------------------------
// K1: zero the U scratch
// ---------------------------------------------------------------------------
__global__ void zero_kernel() {
    size_t idx = (size_t)blockIdx.x * blockDim.x + threadIdx.x;
    size_t n4  = (size_t)NN * KU / 4;
    if (idx < n4) reinterpret_cast<float4*>(g_U)[idx] = make_float4(0.f, 0.f, 0.f, 0.f);
}

// ---------------------------------------------------------------------------
// K2: edge scatter (atomic, proven config). 16 threads per edge; thread t owns
//     dims [4t, 4t+4). msg = w_e*(x[src] + W_edge@ef + b_edge) -> RED.128 to U.
// ---------------------------------------------------------------------------
__global__ void edge_kernel(const float* __restrict__ x,
                            const int*   __restrict__ edge_list,
                            const float* __restrict__ ew,
                            const float* __restrict__ ef,
                            const float* __restrict__ W_edge,
                            const float* __restrict__ b_edge,
                            int E) {
    __shared__ float4 We_sh[EDIM * 16];
    __shared__ float4 be_sh[16];

    int tid = threadIdx.x;
    {
        int d = tid / 16, t = tid % 16;
        float4 v;
        v.x = W_edge[(4 * t + 0) * EDIM + d];
        v.y = W_edge[(4 * t + 1) * EDIM + d];
        v.z = W_edge[(4 * t + 2) * EDIM + d];
        v.w = W_edge[(4 * t + 3) * EDIM + d];
        We_sh[tid] = v;
        if (tid < 16) be_sh[tid] = reinterpret_cast<const float4*>(b_edge)[tid];
    }
    __syncthreads();

    int e = blockIdx.x * 16 + (tid >> 4);
    int t = tid & 15;
    if (e >= E) return;

    int ni  = edge_list[3 * e + 0];
    int no  = edge_list[3 * e + 1];
    int rel = edge_list[3 * e + 2];
    float w = ew[e];

    const float4* efv = reinterpret_cast<const float4*>(ef + (size_t)e * EDIM);
    float4 acc = be_sh[t];
#pragma unroll
    for (int g = 0; g < 4; g++) {
        float4 fg = efv[g];
        float vals[4] = {fg.x, fg.y, fg.z, fg.w};
#pragma unroll
        for (int s = 0; s < 4; s++) {
            float4 wv = We_sh[(4 * g + s) * 16 + t];
            float  fd = vals[s];
            acc.x += wv.x * fd;
            acc.y += wv.y * fd;
            acc.z += wv.z * fd;
            acc.w += wv.w * fd;
        }
    }

    float4 xg = reinterpret_cast<const float4*>(x + (size_t)ni * DD)[t];
    float4 val;
    val.x = w * (xg.x + acc.x);
    val.y = w * (xg.y + acc.y);
    val.z = w * (xg.z + acc.z);
    val.w = w * (xg.w + acc.w);

    float4* dst = reinterpret_cast<float4*>(g_U + ((size_t)no * RR + rel) * DD + 4 * t);
    atomicAdd(dst, val);
}

// ---------------------------------------------------------------------------
// K3: register-blocked GEMM, packed f32x2 FMA, K-split staging (2 x 32KB).
//     out = relu([U‖x](N x 512) @ Wc(512 x 64) + bias)
//     Block: 32 nodes (16 pairs (p, p+16)), 256 threads.
//     Thread (col = t&63, g = t>>6): 1 col x pairs {4g..4g+3}. 4 f32x2 accs.
//     Target: ~60 regs -> 4 blocks/SM (50% occ), warp-coalesced weight LDG.128.
// ---------------------------------------------------------------------------
__global__ __launch_bounds__(256) void out_kernel(const float* __restrict__ x,
                                                  float* __restrict__ out, int Nn) {
    __shared__ __align__(16) ull u2[16 * 256];   // 16 pairs x 256 k-slice, 32 KB
    int tid  = threadIdx.x;
    int base = blockIdx.x * 32;

    int col = tid & 63;
    int g   = tid >> 6;       // 0..3 -> pairs 4g..4g+3

    ull acc[4];
    {
        float b = g_bias[col];
#pragma unroll
        for (int q = 0; q < 4; q++) acc[q] = pk2(b);
    }

#pragma unroll
    for (int h = 0; h < 2; h++) {
        if (h) __syncthreads();

        // ---- stage k in [h*256, h*256+256), packed (node p, node p+16) ----
#pragma unroll
        for (int it = 0; it < 16; it++) {
            int idx = it * 256 + tid;
            int p   = idx >> 8;               // pair 0..15
            int k   = (idx & 255) + h * 256;
            int na  = base + p;
            int nb  = na + 16;
            float a = 0.f, b = 0.f;
            if (k < KU) {
                if (na < Nn) a = g_U[(size_t)na * KU + k];
                if (nb < Nn) b = g_U[(size_t)nb * KU + k];
            } else {
                int kx = k - KU;
                if (na < Nn) a = x[(size_t)na * DD + kx];
                if (nb < Nn) b = x[(size_t)nb * DD + kx];
            }
            float2 v = make_float2(a, b);
            u2[idx] = *reinterpret_cast<ull*>(&v);
        }
        __syncthreads();

        // ---- compute on this K-slice ----
#pragma unroll 2
        for (int kk = 0; kk < 64; kk++) {
            int kg = h * 64 + kk;
            float4 w = __ldg(&g_Wq[kg * 64 + col]);   // W[col][4kg..4kg+3], coalesced
            ull w0 = pk2(w.x), w1 = pk2(w.y), w2 = pk2(w.z), w3 = pk2(w.w);
#pragma unroll
            for (int q = 0; q < 4; q++) {
                const ulonglong2* up =
                    reinterpret_cast<const ulonglong2*>(&u2[(g * 4 + q) * 256 + 4 * kk]);
                ulonglong2 p0 = up[0];   // k+0, k+1   (warp-broadcast LDS.128)
                ulonglong2 p1 = up[1];   // k+2, k+3
                acc[q] = f2fma(w0, p0.x, acc[q]);
                acc[q] = f2fma(w1, p0.y, acc[q]);
                acc[q] = f2fma(w2, p1.x, acc[q]);
                acc[q] = f2fma(w3, p1.y, acc[q]);
            }
        }
    }

    // ---- epilogue: relu + coalesced STG.32 (warp = 32 consecutive cols) ----
#pragma unroll
    for (int q = 0; q < 4; q++) {
        float2 a = up2(acc[q]);
        int p  = g * 4 + q;
        int n0 = base + p;
        int n1 = n0 + 16;
        if (n0 < Nn) out[(size_t)n0 * DD + col] = fmaxf(a.x, 0.f);
        if (n1 < Nn) out[(size_t)n1 * DD + col] = fmaxf(a.y, 0.f);
    }
}

// ---------------------------------------------------------------------------
extern "C" void kernel_launch(void* const* d_in, const int* in_sizes, int n_in,
                              void* d_out, int out_size) {
    const float* x      = (const float*)d_in[0];
    const int*   elist  = (const int*)  d_in[1];
    const float* ew     = (const float*)d_in[2];
    const float* ef     = (const float*)d_in[3];
    const float* W_lin  = (const float*)d_in[4];
    const float* b_lin  = (const float*)d_in[5];
    const float* W_self = (const float*)d_in[6];
    const float* b_self = (const float*)d_in[7];
    const float* W_edge = (const float*)d_in[8];
    const float* b_edge = (const float*)d_in[9];
    float*       out    = (float*)d_out;

    int E = in_sizes[2];            // edge_weight element count
    int N = in_sizes[0] / DD;       // x element count / D

    prep_kernel<<<32, 256>>>(W_lin, b_lin, W_self, b_self);

    {
        size_t n4 = (size_t)NN * KU / 4;
        int blocks = (int)((n4 + 255) / 256);
        zero_kernel<<<blocks, 256>>>();
    }

    {
        int blocks = (E + 15) / 16;
        edge_kernel<<<blocks, 256>>>(x, elist, ew, ef, W_edge, b_edge, E);
    }

    {
        int blocks = (N + 31) / 32;
        out_kernel<<<blocks, 256>>>(x, out, N);
    }
}